// round 3
// baseline (speedup 1.0000x reference)
#include <cuda_runtime.h>
#include <math.h>

// Problem constants (FrameReducer: N=16, T=2048, C=512, V=500)
#define PN 16
#define PT 2048
#define PC 512
#define PV 500
#define NWORDS (PT / 32)   // 64 mask words per row

// Scratch (device globals; no allocation allowed)
__device__ unsigned g_mask[PN * NWORDS]; // keep-bitmask per row
__device__ int g_src[PN * PT];           // g_src[n*PT + r] = source t for rank r
__device__ int g_lens[PN];               // lens_fr per batch row

// threshold: float32(log(0.9)) — matches jnp float32 weak-typed comparison
#define LOG09 (-0.10536051565782628f)

// ---------------------------------------------------------------------------
// Robust x_lens read: JAX with x64 disabled dumps int32 despite astype(int64).
// Detect dtype from the first 64 bytes only (always in-bounds):
//   int64 layout: words[1,3,...,15] are high words of values in [1,2048] -> 0
//   int32 layout: words[1,3,...,15] are lens[1],lens[3],... in [1,2048] -> !=0
// ---------------------------------------------------------------------------
__device__ __forceinline__ long long read_xlen(const void* p, int n) {
    const int* w = (const int*)p;
    bool is64 = true;
#pragma unroll
    for (int i = 1; i < 16; i += 2) {
        if (w[i] != 0) { is64 = false; break; }
    }
    if (is64) return ((const long long*)p)[n];
    return (long long)w[n];
}

// ---------------------------------------------------------------------------
// Kernel 1: mask. 128 blocks (16 rows x 8 chunks) x 256 threads, 1 load each.
// Spreads the scattered blank-channel loads across 128 SMs -> latency hidden.
// ---------------------------------------------------------------------------
__global__ void mask_kernel(const float* __restrict__ ctc,
                            const void* __restrict__ x_lens,
                            const int* __restrict__ blank_ptr) {
    const int n     = blockIdx.x >> 3;         // 0..15
    const int chunk = blockIdx.x & 7;          // 0..7
    const int t     = chunk * 256 + threadIdx.x;
    const int blank = blank_ptr ? blank_ptr[0] : 0;
    const long long xl = read_xlen(x_lens, n);

    bool k = false;
    if ((long long)t < xl) {
        k = (ctc[((size_t)n * PT + t) * PV + blank] < LOG09);
    }
    const unsigned m = __ballot_sync(0xffffffffu, k);
    if ((threadIdx.x & 31) == 0) {
        g_mask[n * NWORDS + (t >> 5)] = m;
    }
}

// ---------------------------------------------------------------------------
// Kernel 2: per-row scan over 64 mask words -> g_src, g_lens, and lens tail.
// 16 blocks x 64 threads. Bitmask is tiny (4KB) and L2-hot.
// ---------------------------------------------------------------------------
__global__ void scan_kernel(float* __restrict__ out, int t_prime, int rem) {
    const int n   = blockIdx.x;
    const int tid = threadIdx.x;               // 0..63
    const int lane = tid & 31;
    const int wrp  = tid >> 5;                 // 0 or 1

    const unsigned m = g_mask[n * NWORDS + tid];
    const int c = __popc(m);

    // inclusive warp scan of counts
    int incl = c;
#pragma unroll
    for (int off = 1; off < 32; off <<= 1) {
        int v = __shfl_up_sync(0xffffffffu, incl, off);
        if (lane >= off) incl += v;
    }

    __shared__ int warp_tot[2];
    if (lane == 31) warp_tot[wrp] = incl;
    __syncthreads();

    int base = incl - c + (wrp == 1 ? warp_tot[0] : 0);   // exclusive prefix
    const int total = warp_tot[0] + warp_tot[1];

    if (tid == 0) {
        g_lens[n] = total;
        // lens tail (second output), each block writes its own row's entry
        if (rem > 0) {
            const size_t off = (size_t)PN * t_prime * PC;
            if (rem == PN) {
                out[off + n] = (float)total;
            } else if (rem == 2 * PN) {
                reinterpret_cast<long long*>(out + off)[n] = (long long)total;
            }
        }
    }

    // emit kept frame indices for this word
    unsigned mm = m;
    int t0 = tid * 32;
    while (mm) {
        int b = __ffs(mm) - 1;
        mm &= mm - 1;
        g_src[n * PT + base] = t0 + b;
        base++;
    }
}

// ---------------------------------------------------------------------------
// Kernel 3: gather/zero-fill. One block per output row (n, r), 128 threads,
// float4 => 128*16B = 2048B = one row of C=512 floats. Every output element
// written exactly once (no memset needed; d_out is poisoned).
// ---------------------------------------------------------------------------
__global__ void gather_kernel(const float* __restrict__ x,
                              float* __restrict__ out,
                              int t_prime) {
    const int r = blockIdx.x % t_prime;
    const int n = blockIdx.x / t_prime;
    const int lane = threadIdx.x;                // 0..127

    float4 val = make_float4(0.f, 0.f, 0.f, 0.f);
    if (r < g_lens[n]) {
        const int t = g_src[n * PT + r];
        val = reinterpret_cast<const float4*>(x + ((size_t)n * PT + t) * PC)[lane];
    }
    reinterpret_cast<float4*>(out + ((size_t)n * t_prime + r) * PC)[lane] = val;
}

// ---------------------------------------------------------------------------
extern "C" void kernel_launch(void* const* d_in, const int* in_sizes, int n_in,
                              void* d_out, int out_size) {
    const float* x      = (const float*)d_in[0];    // [N,T,C] f32
    const void*  x_lens = d_in[1];                  // [N] i32 or i64 (detected)
    const float* ctc    = (const float*)d_in[2];    // [N,T,V] f32
    const int*   blank  = (n_in >= 4) ? (const int*)d_in[3] : nullptr;
    float*       out    = (float*)d_out;

    // T' is fixed by the harness via out_size: out_size = N*T'*C (+ optional lens tail)
    const int row = PN * PC;                 // 8192
    int t_prime = out_size / row;
    int rem = out_size - t_prime * row;
    if (t_prime < 1) t_prime = 1;

    mask_kernel<<<PN * 8, 256>>>(ctc, x_lens, blank);
    scan_kernel<<<PN, 64>>>(out, t_prime, rem);
    gather_kernel<<<PN * t_prime, 128>>>(x, out, t_prime);
}